// round 2
// baseline (speedup 1.0000x reference)
#include <cuda_runtime.h>
#include <math.h>

// ---------------- scratch (static device globals; no runtime allocation) ----
__device__ float g_kv  [4L*1024*4096];   // 64 MB  : kv after 1x1 conv
__device__ float g_k   [4L*512*4096];    // 32 MB  : normalized k
__device__ float g_v   [4L*512*4096];    // 32 MB  : v
__device__ float g_qpre[4L*512*4096];    // 32 MB  : q after 1x1 conv
__device__ float g_q   [4L*512*4096];    // 32 MB  : q after dense conv (then normalized in place)
__device__ float g_part[16L*32*64*64];   // 8 MB   : attention K-split partials
__device__ float g_attn[32L*64*64];      // softmaxed attention
__device__ float g_wp2 [4L*512*512];     // folded per-batch projection weights

// ---------------- generic tiled SGEMM: C[b] = A[b?] @ B[b] ------------------
// A: [M,K] row-major weights (optionally per-batch, stride aBS)
// B: [K,N] row-major activations, per-batch stride bBS
// CONV3: A is [M,K,3] and B columns are shifted by tap-1 (zero padded) -> k=3 conv
#define BM 128
#define BN 128
#define BKK 8

template <bool CONV3>
__global__ void __launch_bounds__(256) gemm_k(
    const float* __restrict__ A, const float* __restrict__ B, float* __restrict__ C,
    int M, int N, int K, long aBS, long bBS, long cBS)
{
    __shared__ float As[BKK][BM];
    __shared__ float Bs[BKK][BN];

    const int tid = threadIdx.x;
    const int bx = blockIdx.x, by = blockIdx.y, bz = blockIdx.z;
    const float* Ab = A + (long)bz * aBS;
    const float* Bb = B + (long)bz * bBS;
    float*       Cb = C + (long)bz * cBS;

    const int tx = tid & 15, ty = tid >> 4;

    float acc[8][8];
#pragma unroll
    for (int i = 0; i < 8; i++)
#pragma unroll
        for (int j = 0; j < 8; j++) acc[i][j] = 0.f;

    const int aRow = tid >> 1;          // 0..127
    const int aK0  = (tid & 1) * 4;     // 0 or 4
    const int bK   = tid >> 5;          // 0..7
    const int bC   = (tid & 31) * 4;    // 0..124

    const int ntaps = CONV3 ? 3 : 1;
    for (int tap = 0; tap < ntaps; ++tap) {
        const int shift = CONV3 ? (tap - 1) : 0;
        for (int k0 = 0; k0 < K; k0 += BKK) {
            // load A tile (128 rows x 8 k), store transposed As[k][row]
#pragma unroll
            for (int i = 0; i < 4; i++) {
                const int kk = aK0 + i;
                long aidx;
                if (CONV3) aidx = (long)(by*BM + aRow) * (3L*K) + (long)(k0+kk)*3 + tap;
                else       aidx = (long)(by*BM + aRow) * K + (k0 + kk);
                As[kk][aRow] = Ab[aidx];
            }
            // load B tile (8 k x 128 cols)
            if (!CONV3) {
                const float4 v = *reinterpret_cast<const float4*>(
                    &Bb[(long)(k0 + bK) * N + bx*BN + bC]);
                *reinterpret_cast<float4*>(&Bs[bK][bC]) = v;
            } else {
#pragma unroll
                for (int i = 0; i < 4; i++) {
                    const int gcol = bx*BN + bC + i + shift;
                    Bs[bK][bC + i] = (gcol >= 0 && gcol < N)
                        ? Bb[(long)(k0 + bK) * N + gcol] : 0.f;
                }
            }
            __syncthreads();
#pragma unroll
            for (int kk = 0; kk < BKK; ++kk) {
                float a[8], b[8];
#pragma unroll
                for (int i = 0; i < 8; i++) a[i] = As[kk][ty*8 + i];
#pragma unroll
                for (int j = 0; j < 8; j++) b[j] = Bs[kk][tx*8 + j];
#pragma unroll
                for (int i = 0; i < 8; i++)
#pragma unroll
                    for (int j = 0; j < 8; j++) acc[i][j] += a[i] * b[j];
            }
            __syncthreads();
        }
    }
    // epilogue: dims are exact multiples of tiles here, no bounds checks
#pragma unroll
    for (int i = 0; i < 8; i++) {
        float* crow = Cb + (long)(by*BM + ty*8 + i) * N + bx*BN + tx*8;
        *reinterpret_cast<float4*>(crow)     = make_float4(acc[i][0], acc[i][1], acc[i][2], acc[i][3]);
        *reinterpret_cast<float4*>(crow + 4) = make_float4(acc[i][4], acc[i][5], acc[i][6], acc[i][7]);
    }
}

// ---------------- depthwise k=3 conv + split + L2-norm of k rows ------------
// one block per (channel c in 0..1023, batch b); row length 4096
__global__ void __launch_bounds__(256) dwnorm_k(
    const float* __restrict__ kv, const float* __restrict__ wdw,
    float* __restrict__ kout, float* __restrict__ vout)
{
    const int c = blockIdx.x;   // 0..1023
    const int b = blockIdx.y;
    const int tid = threadIdx.x;
    const float* row = kv + ((long)b*1024 + c) * 4096;
    const float w0 = wdw[c*3+0], w1 = wdw[c*3+1], w2 = wdw[c*3+2];

    float vals[16];
    float ss = 0.f;
#pragma unroll
    for (int i = 0; i < 16; i++) {
        const int t = tid + i*256;
        const float l = (t > 0)    ? row[t-1] : 0.f;
        const float m = row[t];
        const float r = (t < 4095) ? row[t+1] : 0.f;
        const float v = l*w0 + m*w1 + r*w2;
        vals[i] = v; ss += v*v;
    }
    if (c < 512) {
        __shared__ float red[8];
#pragma unroll
        for (int o = 16; o > 0; o >>= 1) ss += __shfl_xor_sync(0xffffffffu, ss, o);
        if ((tid & 31) == 0) red[tid >> 5] = ss;
        __syncthreads();
        if (tid == 0) {
            float s = 0.f;
            for (int w = 0; w < 8; w++) s += red[w];
            red[0] = s;
        }
        __syncthreads();
        const float rn = 1.f / fmaxf(sqrtf(red[0]), 1e-12f);
        float* out = kout + ((long)b*512 + c) * 4096;
#pragma unroll
        for (int i = 0; i < 16; i++) out[tid + i*256] = vals[i] * rn;
    } else {
        float* out = vout + ((long)b*512 + (c - 512)) * 4096;
#pragma unroll
        for (int i = 0; i < 16; i++) out[tid + i*256] = vals[i];
    }
}

// ---------------- in-place L2-norm over rows of 4096 ------------------------
__global__ void __launch_bounds__(256) l2norm_k(float* __restrict__ q)
{
    const int c = blockIdx.x, b = blockIdx.y;
    float* row = q + ((long)b*512 + c) * 4096;
    const int tid = threadIdx.x;
    float vals[16];
    float ss = 0.f;
#pragma unroll
    for (int i = 0; i < 16; i++) {
        vals[i] = row[tid + i*256];
        ss += vals[i] * vals[i];
    }
    __shared__ float red[8];
#pragma unroll
    for (int o = 16; o > 0; o >>= 1) ss += __shfl_xor_sync(0xffffffffu, ss, o);
    if ((tid & 31) == 0) red[tid >> 5] = ss;
    __syncthreads();
    if (tid == 0) {
        float s = 0.f;
        for (int w = 0; w < 8; w++) s += red[w];
        red[0] = s;
    }
    __syncthreads();
    const float rn = 1.f / fmaxf(sqrtf(red[0]), 1e-12f);
#pragma unroll
    for (int i = 0; i < 16; i++) row[tid + i*256] = vals[i] * rn;
}

// ---------------- attention partials: attn[c,d] = sum_t q[c,t] k[d,t] -------
// K=4096 split into KS=16 chunks of 256 for parallelism (512 blocks total)
__global__ void __launch_bounds__(256) attn_part_k(
    const float* __restrict__ q, const float* __restrict__ kk,
    float* __restrict__ part)
{
    const int ks = blockIdx.x, h = blockIdx.y, b = blockIdx.z;
    const int bh = b*8 + h;
    __shared__ float qs[32][65];
    __shared__ float ksm[32][65];
    const int tid = threadIdx.x;
    const int lc  = tid >> 2;         // 0..63 (channel within head)
    const int lt0 = (tid & 3) * 8;    // 0,8,16,24
    const float* qbase = q  + ((long)b*512 + h*64) * 4096 + ks*256;
    const float* kbase = kk + ((long)b*512 + h*64) * 4096 + ks*256;
    const int tx = tid & 15, ty = tid >> 4;

    float acc[4][4] = {};
    for (int kc = 0; kc < 256; kc += 32) {
#pragma unroll
        for (int i = 0; i < 8; i++) {
            const int t = lt0 + i;
            qs [t][lc] = qbase[(long)lc*4096 + kc + t];
            ksm[t][lc] = kbase[(long)lc*4096 + kc + t];
        }
        __syncthreads();
#pragma unroll
        for (int t = 0; t < 32; t++) {
            float a[4], bb[4];
#pragma unroll
            for (int i = 0; i < 4; i++) a[i]  = qs [t][ty*4 + i];
#pragma unroll
            for (int j = 0; j < 4; j++) bb[j] = ksm[t][tx*4 + j];
#pragma unroll
            for (int i = 0; i < 4; i++)
#pragma unroll
                for (int j = 0; j < 4; j++) acc[i][j] += a[i] * bb[j];
        }
        __syncthreads();
    }
    float* pb = part + ((long)ks*32 + bh) * 64 * 64;
#pragma unroll
    for (int i = 0; i < 4; i++)
#pragma unroll
        for (int j = 0; j < 4; j++)
            pb[(ty*4 + i)*64 + tx*4 + j] = acc[i][j];
}

// ---------------- reduce partials, * temperature, softmax over d ------------
__global__ void __launch_bounds__(256) softmax_k(
    const float* __restrict__ part, const float* __restrict__ temp,
    float* __restrict__ attn)
{
    const int h = blockIdx.x, b = blockIdx.y;
    const int bh = b*8 + h;
    __shared__ float sm[64][64];
    const int tid = threadIdx.x;
    const float tpr = temp[h];
    for (int idx = tid; idx < 4096; idx += 256) {
        float s = 0.f;
#pragma unroll
        for (int ks = 0; ks < 16; ks++)
            s += part[((long)ks*32 + bh) * 4096 + idx];
        sm[idx >> 6][idx & 63] = s * tpr;
    }
    __syncthreads();
    if (tid < 64) {
        float mx = -INFINITY;
#pragma unroll
        for (int d = 0; d < 64; d++) mx = fmaxf(mx, sm[tid][d]);
        float e[64];
        float sum = 0.f;
#pragma unroll
        for (int d = 0; d < 64; d++) { e[d] = expf(sm[tid][d] - mx); sum += e[d]; }
        const float inv = 1.f / sum;
        float* out = attn + (long)bh * 4096 + tid * 64;
#pragma unroll
        for (int d = 0; d < 64; d++) out[d] = e[d] * inv;
    }
}

// ---------------- fold attention into projection weights --------------------
// Wp2[b][o, h*64+d] = sum_cc Wp[o, h*64+cc] * attn[b,h,cc,d]
__global__ void __launch_bounds__(256) wp2_k(
    const float* __restrict__ wp, const float* __restrict__ attn,
    float* __restrict__ wp2)
{
    const int ot = blockIdx.x, h = blockIdx.y, b = blockIdx.z;
    const int bh = b*8 + h;
    __shared__ float at [64][64];
    __shared__ float wpt[64][65];
    const int tid = threadIdx.x;
    for (int idx = tid; idx < 4096; idx += 256) {
        const int r = idx >> 6, cidx = idx & 63;
        at [r][cidx] = attn[(long)bh*4096 + idx];
        wpt[r][cidx] = wp[(long)(ot*64 + r)*512 + h*64 + cidx];
    }
    __syncthreads();
    const int tx = tid & 15, ty = tid >> 4;
    float acc[4][4] = {};
    for (int cc = 0; cc < 64; cc++) {
        float a[4], bb[4];
#pragma unroll
        for (int i = 0; i < 4; i++) a[i]  = wpt[ty*4 + i][cc];
#pragma unroll
        for (int j = 0; j < 4; j++) bb[j] = at[cc][tx*4 + j];
#pragma unroll
        for (int i = 0; i < 4; i++)
#pragma unroll
            for (int j = 0; j < 4; j++) acc[i][j] += a[i] * bb[j];
    }
#pragma unroll
    for (int i = 0; i < 4; i++)
#pragma unroll
        for (int j = 0; j < 4; j++)
            wp2[(long)b*512*512 + (long)(ot*64 + ty*4 + i)*512 + h*64 + tx*4 + j]
                = acc[i][j];
}

// ---------------------------------------------------------------------------
extern "C" void kernel_launch(void* const* d_in, const int* in_sizes, int n_in,
                              void* d_out, int out_size)
{
    const float* x       = (const float*)d_in[0];
    const float* y       = (const float*)d_in[1];
    const float* w_kv    = (const float*)d_in[2];
    const float* w_kv_dw = (const float*)d_in[3];
    const float* w_q     = (const float*)d_in[4];
    const float* w_q_dw  = (const float*)d_in[5];
    const float* w_proj  = (const float*)d_in[6];
    const float* temp    = (const float*)d_in[7];
    float* out = (float*)d_out;

    float *kv, *kb, *vb, *qpre, *qb, *partb, *attnb, *wp2b;
    cudaGetSymbolAddress((void**)&kv,    g_kv);
    cudaGetSymbolAddress((void**)&kb,    g_k);
    cudaGetSymbolAddress((void**)&vb,    g_v);
    cudaGetSymbolAddress((void**)&qpre,  g_qpre);
    cudaGetSymbolAddress((void**)&qb,    g_q);
    cudaGetSymbolAddress((void**)&partb, g_part);
    cudaGetSymbolAddress((void**)&attnb, g_attn);
    cudaGetSymbolAddress((void**)&wp2b,  g_wp2);

    const dim3 thr(256);

    // 1) kv = W_kv @ x           [1024 x 4096], K=512, batch 4
    gemm_k<false><<<dim3(32, 8, 4), thr>>>(w_kv, x, kv,
        1024, 4096, 512, 0L, 512L*4096, 1024L*4096);

    // 2) q_pre = W_q @ y         [512 x 4096], K=512
    gemm_k<false><<<dim3(32, 4, 4), thr>>>(w_q, y, qpre,
        512, 4096, 512, 0L, 512L*4096, 512L*4096);

    // 3) depthwise k=3 conv on kv; split into k (L2-normalized rows) and v
    dwnorm_k<<<dim3(1024, 4), thr>>>(kv, w_kv_dw, kb, vb);

    // 4) q = dense k=3 conv of q_pre  (3 shifted GEMMs folded in-kernel)
    gemm_k<true><<<dim3(32, 4, 4), thr>>>(w_q_dw, qpre, qb,
        512, 4096, 512, 0L, 512L*4096, 512L*4096);

    // 5) L2-normalize q rows in place
    l2norm_k<<<dim3(512, 4), thr>>>(qb);

    // 6) attention partials over 16 K-splits
    attn_part_k<<<dim3(16, 8, 4), thr>>>(qb, kb, partb);

    // 7) reduce + temperature + softmax
    softmax_k<<<dim3(8, 4), thr>>>(partb, temp, attnb);

    // 8) fold attention into projection: Wp2 = blockdiag-apply(W_proj, attn)
    wp2_k<<<dim3(8, 8, 4), thr>>>(w_proj, attnb, wp2b);

    // 9) out = Wp2[b] @ v[b]   (fused attn@v + 1x1 projection)
    gemm_k<false><<<dim3(32, 4, 4), thr>>>(wp2b, vb, out,
        512, 4096, 512, 512L*512, 512L*4096, 512L*4096);
}

// round 8
// speedup vs baseline: 4.8809x; 4.8809x over previous
#include <cuda_runtime.h>
#include <cuda_bf16.h>
#include <math.h>
#include <stdint.h>

typedef __nv_bfloat16 BF16;

// ---------------- scratch -----------------
__device__ float g_kv  [4L*1024*4096];
__device__ float g_k   [4L*512*4096];
__device__ float g_v   [4L*512*4096];
__device__ float g_qpre[4L*512*4096];
__device__ float g_q   [4L*512*4096];
__device__ float g_part[16L*32*64*64];
__device__ float g_attn[32L*64*64];
__device__ float g_wp2 [4L*512*512];
__device__ BF16 g_wkvh[1024L*512], g_wkvl[1024L*512];
__device__ BF16 g_wqh [512L*512],  g_wql [512L*512];
__device__ BF16 g_wth [3L*512*512], g_wtl[3L*512*512];
__device__ BF16 g_w2h [4L*512*512], g_w2l[4L*512*512];
__device__ BF16 g_xTh[4L*4096*512], g_xTl[4L*4096*512];
__device__ BF16 g_yTh[4L*4096*512], g_yTl[4L*4096*512];
__device__ BF16 g_qTh[4L*4096*512], g_qTl[4L*4096*512];
__device__ BF16 g_vTh[4L*4096*512], g_vTl[4L*4096*512];

__device__ __forceinline__ void split_bf16(float x, BF16& h, BF16& l) {
    h = __float2bfloat16(x);
    l = __float2bfloat16(x - __bfloat162float(h));
}

// ---------------- mma helpers (sm_80-level PTX only) -----------------
#define LDSM4(r, a) asm volatile( \
    "ldmatrix.sync.aligned.m8n8.x4.shared.b16 {%0,%1,%2,%3},[%4];" \
    : "=r"((r)[0]),"=r"((r)[1]),"=r"((r)[2]),"=r"((r)[3]) : "r"(a))
#define LDSM2(r, a) asm volatile( \
    "ldmatrix.sync.aligned.m8n8.x2.shared.b16 {%0,%1},[%2];" \
    : "=r"((r)[0]),"=r"((r)[1]) : "r"(a))
#define MMA16816(d, a, b) asm volatile( \
    "mma.sync.aligned.m16n8k16.row.col.f32.bf16.bf16.f32 " \
    "{%0,%1,%2,%3},{%4,%5,%6,%7},{%8,%9},{%0,%1,%2,%3};" \
    : "+f"((d)[0]),"+f"((d)[1]),"+f"((d)[2]),"+f"((d)[3]) \
    : "r"((a)[0]),"r"((a)[1]),"r"((a)[2]),"r"((a)[3]),"r"((b)[0]),"r"((b)[1]))
__device__ __forceinline__ void cp16(uint32_t dst, const void* src) {
    asm volatile("cp.async.cg.shared.global [%0],[%1],16;" :: "r"(dst), "l"(src) : "memory");
}
__device__ __forceinline__ void st16z(uint32_t dst) {
    asm volatile("st.shared.v4.u32 [%0],{%1,%1,%1,%1};" :: "r"(dst), "r"(0u) : "memory");
}
#define CP_COMMIT() asm volatile("cp.async.commit_group;" ::: "memory")
#define CP_WAIT(n)  asm volatile("cp.async.wait_group %0;" :: "n"(n) : "memory")

// ---------------- HMMA GEMM ----------------
// C[M,4096] = sum_tap A[tap][M,512] @ B(row-shifted)[4096,512]^T
// A,B K-major bf16 hi/lo. CTA 128m x 64n, 128 thr, warp tile 64x32, K-slab 32.
// smem per stage (bytes): AH 0..10240, AL 10240, BH 20480, BL 25600; stage=30720.
#define GSMEM 61440
template<int TAPS>
__global__ void __launch_bounds__(128) gemm_mma(
    const BF16* __restrict__ Ah, const BF16* __restrict__ Al,
    const BF16* __restrict__ Bh, const BF16* __restrict__ Bl,
    float* __restrict__ C, long aBS, long bBS, long cBS)
{
    extern __shared__ char smraw[];
    const uint32_t smb = (uint32_t)__cvta_generic_to_shared(smraw);
    const int tid = threadIdx.x, lane = tid & 31, wid = tid >> 5;
    const int wm = wid & 1, wn = wid >> 1;
    const int nt = blockIdx.x, mt = blockIdx.y, bz = blockIdx.z;
    Ah += (size_t)bz * aBS;  Al += (size_t)bz * aBS;
    Bh += (size_t)bz * bBS;  Bl += (size_t)bz * bBS;
    float* Cb = C + (size_t)bz * cBS;

    const int S = TAPS * 16;

    auto load_slab = [&](int s) {
        const int tap = (TAPS == 3) ? (s >> 4) : 0;
        const int ks  = (TAPS == 3) ? (s & 15) : s;
        const int k0  = ks * 32;
        const int shift = (TAPS == 3) ? (tap - 1) : 0;
        const BF16* ah = Ah + (size_t)tap * 262144;
        const BF16* al = Al + (size_t)tap * 262144;
        const uint32_t st = smb + (uint32_t)(s & 1) * 30720;
#pragma unroll
        for (int i = 0; i < 4; ++i) {            // A: 512 16B chunks
            const int c = tid + i * 128;
            const int r = c >> 2, cc = c & 3;
            const uint32_t dst = st + r * 80 + cc * 16;
            const size_t g = (size_t)(mt * 128 + r) * 512 + k0 + cc * 8;
            cp16(dst,         ah + g);
            cp16(dst + 10240, al + g);
        }
#pragma unroll
        for (int i = 0; i < 2; ++i) {            // B: 256 16B chunks
            const int c = tid + i * 128;
            const int r = c >> 2, cc = c & 3;
            const int rg = nt * 64 + r + shift;
            const uint32_t dst = st + 20480 + r * 80 + cc * 16;
            if (TAPS == 1 || (unsigned)rg < 4096u) {
                const size_t g = (size_t)rg * 512 + k0 + cc * 8;
                cp16(dst,        Bh + g);
                cp16(dst + 5120, Bl + g);
            } else {
                st16z(dst);
                st16z(dst + 5120);
            }
        }
    };

    float acc[4][4][4];
#pragma unroll
    for (int i = 0; i < 4; ++i)
#pragma unroll
        for (int j = 0; j < 4; ++j)
#pragma unroll
            for (int k = 0; k < 4; ++k) acc[i][j][k] = 0.f;

    load_slab(0);
    CP_COMMIT();

    for (int s = 0; s < S; ++s) {
        if (s + 1 < S) { load_slab(s + 1); CP_COMMIT(); CP_WAIT(1); }
        else           { CP_WAIT(0); }
        __syncthreads();

        const uint32_t st = smb + (uint32_t)(s & 1) * 30720;
#pragma unroll
        for (int kstep = 0; kstep < 2; ++kstep) {
            uint32_t aH[4][4], aL[4][4], bH[4][2], bL[4][2];
#pragma unroll
            for (int tm = 0; tm < 4; ++tm) {
                const int m = wm * 64 + tm * 16 + (lane & 15);
                const int kk = kstep * 16 + (lane >> 4) * 8;
                const uint32_t ad = st + m * 80 + kk * 2;
                LDSM4(aH[tm], ad);
                LDSM4(aL[tm], ad + 10240);
            }
#pragma unroll
            for (int tn = 0; tn < 4; ++tn) {
                const int n = wn * 32 + tn * 8 + (lane & 7);
                const int kk = kstep * 16 + ((lane >> 3) & 1) * 8;
                const uint32_t bd = st + 20480 + n * 80 + kk * 2;
                LDSM2(bH[tn], bd);
                LDSM2(bL[tn], bd + 5120);
            }
#pragma unroll
            for (int tm = 0; tm < 4; ++tm)
#pragma unroll
                for (int tn = 0; tn < 4; ++tn) {
                    MMA16816(acc[tm][tn], aH[tm], bH[tn]);
                    MMA16816(acc[tm][tn], aH[tm], bL[tn]);
                    MMA16816(acc[tm][tn], aL[tm], bH[tn]);
                }
        }
        __syncthreads();
    }

    // epilogue: fragment layout -> global f32
#pragma unroll
    for (int tm = 0; tm < 4; ++tm) {
        const int row0 = mt * 128 + wm * 64 + tm * 16 + (lane >> 2);
#pragma unroll
        for (int tn = 0; tn < 4; ++tn) {
            const int col = nt * 64 + wn * 32 + tn * 8 + (lane & 3) * 2;
            *(float2*)&Cb[(size_t)row0 * 4096 + col] =
                make_float2(acc[tm][tn][0], acc[tm][tn][1]);
            *(float2*)&Cb[(size_t)(row0 + 8) * 4096 + col] =
                make_float2(acc[tm][tn][2], acc[tm][tn][3]);
        }
    }
}

// ---------------- converts -----------------
__global__ void __launch_bounds__(256) cvt_pair_k(
    const float* __restrict__ in, BF16* __restrict__ oh, BF16* __restrict__ ol, int n)
{
    const int i = blockIdx.x * 256 + threadIdx.x;
    if (i < n) { BF16 h, l; split_bf16(in[i], h, l); oh[i] = h; ol[i] = l; }
}
__global__ void __launch_bounds__(256) cvt_wtap_k(
    const float* __restrict__ w, BF16* __restrict__ oh, BF16* __restrict__ ol)
{
    const int i = blockIdx.x * 256 + threadIdx.x;
    if (i < 3 * 512 * 512) {
        const int t = i / 262144, r = i % 262144;
        const int m = r >> 9, k = r & 511;
        BF16 h, l; split_bf16(w[m * 1536 + k * 3 + t], h, l);
        oh[i] = h; ol[i] = l;
    }
}
// f32 [512][4096] -> bf16 pair [4096][512]
__global__ void __launch_bounds__(256) transpose_cvt_k(
    const float* __restrict__ in, BF16* __restrict__ oh, BF16* __restrict__ ol)
{
    __shared__ float smt[32][33];
    const int l0 = blockIdx.x * 32, c0 = blockIdx.y * 32, b = blockIdx.z;
    const float* ib = in + (size_t)b * 512 * 4096;
    BF16* ohb = oh + (size_t)b * 4096 * 512;
    BF16* olb = ol + (size_t)b * 4096 * 512;
    const int tx = threadIdx.x & 31, ty = threadIdx.x >> 5;
#pragma unroll
    for (int k = 0; k < 4; ++k)
        smt[ty + k * 8][tx] = ib[(size_t)(c0 + ty + k * 8) * 4096 + l0 + tx];
    __syncthreads();
#pragma unroll
    for (int k = 0; k < 4; ++k) {
        BF16 h, l; split_bf16(smt[tx][ty + k * 8], h, l);
        const size_t o = (size_t)(l0 + ty + k * 8) * 512 + c0 + tx;
        ohb[o] = h; olb[o] = l;
    }
}

// ---------------- dwconv+norm / l2norm / attention (proven SIMT) ------------
__global__ void __launch_bounds__(256) dwnorm_k(
    const float* __restrict__ kv, const float* __restrict__ wdw,
    float* __restrict__ kout, float* __restrict__ vout)
{
    const int c = blockIdx.x, b = blockIdx.y, tid = threadIdx.x;
    const float* row = kv + ((size_t)b * 1024 + c) * 4096;
    const float w0 = wdw[c*3+0], w1 = wdw[c*3+1], w2 = wdw[c*3+2];
    float vals[16]; float ss = 0.f;
#pragma unroll
    for (int i = 0; i < 16; i++) {
        const int t = tid + i * 256;
        const float l = (t > 0) ? row[t-1] : 0.f;
        const float m = row[t];
        const float r = (t < 4095) ? row[t+1] : 0.f;
        const float v = l*w0 + m*w1 + r*w2;
        vals[i] = v; ss += v * v;
    }
    if (c < 512) {
        __shared__ float red[8];
#pragma unroll
        for (int o = 16; o > 0; o >>= 1) ss += __shfl_xor_sync(0xffffffffu, ss, o);
        if ((tid & 31) == 0) red[tid >> 5] = ss;
        __syncthreads();
        if (tid == 0) { float s = 0.f; for (int w = 0; w < 8; w++) s += red[w]; red[0] = s; }
        __syncthreads();
        const float rn = 1.f / fmaxf(sqrtf(red[0]), 1e-12f);
        float* out = kout + ((size_t)b * 512 + c) * 4096;
#pragma unroll
        for (int i = 0; i < 16; i++) out[tid + i*256] = vals[i] * rn;
    } else {
        float* out = vout + ((size_t)b * 512 + (c - 512)) * 4096;
#pragma unroll
        for (int i = 0; i < 16; i++) out[tid + i*256] = vals[i];
    }
}
__global__ void __launch_bounds__(256) l2norm_k(float* __restrict__ q)
{
    const int c = blockIdx.x, b = blockIdx.y, tid = threadIdx.x;
    float* row = q + ((size_t)b * 512 + c) * 4096;
    float vals[16]; float ss = 0.f;
#pragma unroll
    for (int i = 0; i < 16; i++) { vals[i] = row[tid + i*256]; ss += vals[i]*vals[i]; }
    __shared__ float red[8];
#pragma unroll
    for (int o = 16; o > 0; o >>= 1) ss += __shfl_xor_sync(0xffffffffu, ss, o);
    if ((tid & 31) == 0) red[tid >> 5] = ss;
    __syncthreads();
    if (tid == 0) { float s = 0.f; for (int w = 0; w < 8; w++) s += red[w]; red[0] = s; }
    __syncthreads();
    const float rn = 1.f / fmaxf(sqrtf(red[0]), 1e-12f);
#pragma unroll
    for (int i = 0; i < 16; i++) row[tid + i*256] = vals[i] * rn;
}
__global__ void __launch_bounds__(256) attn_part_k(
    const float* __restrict__ q, const float* __restrict__ kk, float* __restrict__ part)
{
    const int ks = blockIdx.x, h = blockIdx.y, b = blockIdx.z;
    const int bh = b * 8 + h;
    __shared__ float qs[32][65];
    __shared__ float ksm[32][65];
    const int tid = threadIdx.x;
    const int lc = tid >> 2, lt0 = (tid & 3) * 8;
    const float* qbase = q  + ((size_t)b*512 + h*64) * 4096 + ks*256;
    const float* kbase = kk + ((size_t)b*512 + h*64) * 4096 + ks*256;
    const int tx = tid & 15, ty = tid >> 4;
    float acc[4][4] = {};
    for (int kc = 0; kc < 256; kc += 32) {
#pragma unroll
        for (int i = 0; i < 8; i++) {
            const int t = lt0 + i;
            qs [t][lc] = qbase[(size_t)lc*4096 + kc + t];
            ksm[t][lc] = kbase[(size_t)lc*4096 + kc + t];
        }
        __syncthreads();
#pragma unroll
        for (int t = 0; t < 32; t++) {
            float a[4], bb[4];
#pragma unroll
            for (int i = 0; i < 4; i++) a[i]  = qs [t][ty*4 + i];
#pragma unroll
            for (int j = 0; j < 4; j++) bb[j] = ksm[t][tx*4 + j];
#pragma unroll
            for (int i = 0; i < 4; i++)
#pragma unroll
                for (int j = 0; j < 4; j++) acc[i][j] += a[i] * bb[j];
        }
        __syncthreads();
    }
    float* pb = part + ((size_t)ks*32 + bh) * 4096;
#pragma unroll
    for (int i = 0; i < 4; i++)
#pragma unroll
        for (int j = 0; j < 4; j++)
            pb[(ty*4 + i)*64 + tx*4 + j] = acc[i][j];
}
__global__ void __launch_bounds__(256) softmax_k(
    const float* __restrict__ part, const float* __restrict__ temp, float* __restrict__ attn)
{
    const int h = blockIdx.x, b = blockIdx.y;
    const int bh = b * 8 + h;
    __shared__ float smx[64][64];
    const int tid = threadIdx.x;
    const float tpr = temp[h];
    for (int idx = tid; idx < 4096; idx += 256) {
        float s = 0.f;
#pragma unroll
        for (int ks = 0; ks < 16; ks++) s += part[((size_t)ks*32 + bh) * 4096 + idx];
        smx[idx >> 6][idx & 63] = s * tpr;
    }
    __syncthreads();
    if (tid < 64) {
        float mx = -INFINITY;
#pragma unroll
        for (int d = 0; d < 64; d++) mx = fmaxf(mx, smx[tid][d]);
        float e[64]; float sum = 0.f;
#pragma unroll
        for (int d = 0; d < 64; d++) { e[d] = expf(smx[tid][d] - mx); sum += e[d]; }
        const float inv = 1.f / sum;
        float* out = attn + (size_t)bh * 4096 + tid * 64;
#pragma unroll
        for (int d = 0; d < 64; d++) out[d] = e[d] * inv;
    }
}
__global__ void __launch_bounds__(256) wp2_k(
    const float* __restrict__ wp, const float* __restrict__ attn, float* __restrict__ wp2)
{
    const int ot = blockIdx.x, h = blockIdx.y, b = blockIdx.z;
    const int bh = b * 8 + h;
    __shared__ float at [64][64];
    __shared__ float wpt[64][65];
    const int tid = threadIdx.x;
    for (int idx = tid; idx < 4096; idx += 256) {
        const int r = idx >> 6, cidx = idx & 63;
        at [r][cidx] = attn[(size_t)bh*4096 + idx];
        wpt[r][cidx] = wp[(size_t)(ot*64 + r)*512 + h*64 + cidx];
    }
    __syncthreads();
    const int tx = tid & 15, ty = tid >> 4;
    float acc[4][4] = {};
    for (int cc = 0; cc < 64; cc++) {
        float a[4], bb[4];
#pragma unroll
        for (int i = 0; i < 4; i++) a[i]  = wpt[ty*4 + i][cc];
#pragma unroll
        for (int j = 0; j < 4; j++) bb[j] = at[cc][tx*4 + j];
#pragma unroll
        for (int i = 0; i < 4; i++)
#pragma unroll
            for (int j = 0; j < 4; j++) acc[i][j] += a[i] * bb[j];
    }
#pragma unroll
    for (int i = 0; i < 4; i++)
#pragma unroll
        for (int j = 0; j < 4; j++)
            wp2[(size_t)b*262144 + (size_t)(ot*64 + ty*4 + i)*512 + h*64 + tx*4 + j] = acc[i][j];
}

// ---------------------------------------------------------------------------
extern "C" void kernel_launch(void* const* d_in, const int* in_sizes, int n_in,
                              void* d_out, int out_size)
{
    const float* x       = (const float*)d_in[0];
    const float* y       = (const float*)d_in[1];
    const float* w_kv    = (const float*)d_in[2];
    const float* w_kv_dw = (const float*)d_in[3];
    const float* w_q     = (const float*)d_in[4];
    const float* w_q_dw  = (const float*)d_in[5];
    const float* w_proj  = (const float*)d_in[6];
    const float* temp    = (const float*)d_in[7];
    float* out = (float*)d_out;

    float *kv, *kb, *vb, *qpre, *qb, *partb, *attnb, *wp2b;
    BF16 *wkvh, *wkvl, *wqh, *wql, *wth, *wtl, *w2h, *w2l;
    BF16 *xTh, *xTl, *yTh, *yTl, *qTh, *qTl, *vTh, *vTl;
    cudaGetSymbolAddress((void**)&kv, g_kv);     cudaGetSymbolAddress((void**)&kb, g_k);
    cudaGetSymbolAddress((void**)&vb, g_v);      cudaGetSymbolAddress((void**)&qpre, g_qpre);
    cudaGetSymbolAddress((void**)&qb, g_q);      cudaGetSymbolAddress((void**)&partb, g_part);
    cudaGetSymbolAddress((void**)&attnb, g_attn);cudaGetSymbolAddress((void**)&wp2b, g_wp2);
    cudaGetSymbolAddress((void**)&wkvh, g_wkvh); cudaGetSymbolAddress((void**)&wkvl, g_wkvl);
    cudaGetSymbolAddress((void**)&wqh, g_wqh);   cudaGetSymbolAddress((void**)&wql, g_wql);
    cudaGetSymbolAddress((void**)&wth, g_wth);   cudaGetSymbolAddress((void**)&wtl, g_wtl);
    cudaGetSymbolAddress((void**)&w2h, g_w2h);   cudaGetSymbolAddress((void**)&w2l, g_w2l);
    cudaGetSymbolAddress((void**)&xTh, g_xTh);   cudaGetSymbolAddress((void**)&xTl, g_xTl);
    cudaGetSymbolAddress((void**)&yTh, g_yTh);   cudaGetSymbolAddress((void**)&yTl, g_yTl);
    cudaGetSymbolAddress((void**)&qTh, g_qTh);   cudaGetSymbolAddress((void**)&qTl, g_qTl);
    cudaGetSymbolAddress((void**)&vTh, g_vTh);   cudaGetSymbolAddress((void**)&vTl, g_vTl);

    cudaFuncSetAttribute(gemm_mma<1>, cudaFuncAttributeMaxDynamicSharedMemorySize, GSMEM);
    cudaFuncSetAttribute(gemm_mma<3>, cudaFuncAttributeMaxDynamicSharedMemorySize, GSMEM);

    const dim3 thr(256);
    const long BT = 4096L * 512;

    // weight + input conversions
    cvt_pair_k<<<2048, thr>>>(w_kv, wkvh, wkvl, 1024 * 512);
    cvt_pair_k<<<1024, thr>>>(w_q, wqh, wql, 512 * 512);
    cvt_wtap_k<<<3072, thr>>>(w_q_dw, wth, wtl);
    transpose_cvt_k<<<dim3(128, 16, 4), thr>>>(x, xTh, xTl);
    transpose_cvt_k<<<dim3(128, 16, 4), thr>>>(y, yTh, yTl);

    // kv = Wkv @ x
    gemm_mma<1><<<dim3(64, 8, 4), 128, GSMEM>>>(wkvh, wkvl, xTh, xTl, kv,
        0L, BT, 1024L * 4096);
    // depthwise conv + split + norm(k)
    dwnorm_k<<<dim3(1024, 4), thr>>>(kv, w_kv_dw, kb, vb);
    transpose_cvt_k<<<dim3(128, 16, 4), thr>>>(vb, vTh, vTl);

    // q_pre = Wq @ y ; transpose ; q = conv3(q_pre) ; norm
    gemm_mma<1><<<dim3(64, 4, 4), 128, GSMEM>>>(wqh, wql, yTh, yTl, qpre,
        0L, BT, 512L * 4096);
    transpose_cvt_k<<<dim3(128, 16, 4), thr>>>(qpre, qTh, qTl);
    gemm_mma<3><<<dim3(64, 4, 4), 128, GSMEM>>>(wth, wtl, qTh, qTl, qb,
        0L, BT, 512L * 4096);
    l2norm_k<<<dim3(512, 4), thr>>>(qb);

    // attention + fold into projection
    attn_part_k<<<dim3(16, 8, 4), thr>>>(qb, kb, partb);
    softmax_k<<<dim3(8, 4), thr>>>(partb, temp, attnb);
    wp2_k<<<dim3(8, 8, 4), thr>>>(w_proj, attnb, wp2b);
    cvt_pair_k<<<4096, thr>>>(wp2b, w2h, w2l, 4 * 512 * 512);

    // out = Wp2[b] @ v[b]
    gemm_mma<1><<<dim3(64, 4, 4), 128, GSMEM>>>(w2h, w2l, vTh, vTl, out,
        262144L, BT, 512L * 4096);
}